// round 3
// baseline (speedup 1.0000x reference)
#include <cuda_runtime.h>
#include <cuda_bf16.h>

#define TBINS 100000
#define SCAN_TPB 512
#define NSCAN_BLOCKS ((TBINS + SCAN_TPB - 1) / SCAN_TPB)   // 196

// bins[t] = { sum(exp(lh)), sum(exp(lh)*ev), sum(lh*ev), sum(ev) }
__device__ float4 g_bins[TBINS];
__device__ double g_blockSum[NSCAN_BLOCKS];
__device__ double g_blockOff[NSCAN_BLOCKS];
__device__ double g_pll_sum;
__device__ int    g_cnt;

// ---------------------------------------------------------------- zero
__global__ void zero_kernel() {
    int i = blockIdx.x * blockDim.x + threadIdx.x;
    for (; i < TBINS; i += gridDim.x * blockDim.x)
        g_bins[i] = make_float4(0.f, 0.f, 0.f, 0.f);
    if (blockIdx.x == 0 && threadIdx.x == 0) {
        g_pll_sum = 0.0;
        g_cnt = 0;
    }
}

// ---------------------------------------------------------------- accumulate
__device__ __forceinline__ void acc_one(float lh, int t, int e) {
    float hz = expf(lh);
    float fe = (float)e;
    float4* p = &g_bins[t];
    asm volatile(
        "red.global.add.v4.f32 [%0], {%1, %2, %3, %4};"
        :: "l"(p), "f"(hz), "f"(hz * fe), "f"(lh * fe), "f"(fe)
        : "memory");
}

__global__ void accum_kernel(const float4* __restrict__ in,
                             const int4*  __restrict__ tgt,
                             const int4*  __restrict__ ev,
                             int n4, int n) {
    int i = blockIdx.x * blockDim.x + threadIdx.x;
    if (i < n4) {
        float4 lh = in[i];
        int4   t  = tgt[i];
        int4   e  = ev[i];
        acc_one(lh.x, t.x, e.x);
        acc_one(lh.y, t.y, e.y);
        acc_one(lh.z, t.z, e.z);
        acc_one(lh.w, t.w, e.w);
    }
    // tail (n not multiple of 4) handled by global thread 0
    if (i == 0) {
        const float* fin = (const float*)in;
        const int*   it  = (const int*)tgt;
        const int*   ie  = (const int*)ev;
        for (int k = n4 * 4; k < n; ++k) acc_one(fin[k], it[k], ie[k]);
    }
}

// ---------------------------------------------------------------- block sums of A
__global__ void blocksum_kernel() {
    __shared__ double s[SCAN_TPB];
    int b = blockIdx.x, i = threadIdx.x;
    int t = b * SCAN_TPB + i;
    s[i] = (t < TBINS) ? (double)g_bins[t].x : 0.0;
    __syncthreads();
    for (int off = SCAN_TPB / 2; off > 0; off >>= 1) {
        if (i < off) s[i] += s[i + off];
        __syncthreads();
    }
    if (i == 0) g_blockSum[b] = s[0];
}

// ---------------------------------------------------------------- suffix offsets (196 entries, trivial)
__global__ void offset_kernel() {
    if (threadIdx.x == 0) {
        double acc = 0.0;
        for (int b = NSCAN_BLOCKS - 1; b >= 0; --b) {
            g_blockOff[b] = acc;
            acc += g_blockSum[b];
        }
    }
}

// ---------------------------------------------------------------- per-bin suffix + Efron terms
__global__ void efron_kernel() {
    __shared__ double s[SCAN_TPB];
    int b = blockIdx.x, i = threadIdx.x;
    int t = b * SCAN_TPB + i;

    float4 bin = (t < TBINS) ? g_bins[t] : make_float4(0.f, 0.f, 0.f, 0.f);
    s[i] = (double)bin.x;
    __syncthreads();
    // Hillis-Steele suffix-inclusive scan
    for (int off = 1; off < SCAN_TPB; off <<= 1) {
        double v = s[i];
        if (i + off < SCAN_TPB) v += s[i + off];
        __syncthreads();
        s[i] = v;
        __syncthreads();
    }
    double D = s[i] + g_blockOff[b];   // risk-set sum for time t

    double pll = 0.0;
    int inc = 0;
    int m = (int)(bin.w + 0.5f);
    if (t < TBINS && m > 0) {
        float Df   = (float)D;
        float T    = bin.y;
        float invm = 1.0f / (float)m;
        float ld   = 0.0f;
        for (int l = 0; l < m; ++l)
            ld += logf(Df - ((float)l * invm) * T);
        pll = (double)bin.z - (double)ld;
        inc = 1;
    }

    int cnt = __syncthreads_count(inc);

    s[i] = pll;
    __syncthreads();
    for (int off = SCAN_TPB / 2; off > 0; off >>= 1) {
        if (i < off) s[i] += s[i + off];
        __syncthreads();
    }
    if (i == 0) {
        atomicAdd(&g_pll_sum, s[0]);
        atomicAdd(&g_cnt, cnt);
    }
}

// ---------------------------------------------------------------- finalize
__global__ void finalize_kernel(float* out) {
    out[0] = (float)(-(g_pll_sum / (double)g_cnt));
}

// ---------------------------------------------------------------- launcher
extern "C" void kernel_launch(void* const* d_in, const int* in_sizes, int n_in,
                              void* d_out, int out_size) {
    const float* inp = (const float*)d_in[0];
    const int*   tgt = (const int*)d_in[1];
    const int*   ev  = (const int*)d_in[2];
    float* out = (float*)d_out;
    int n  = in_sizes[0];
    int n4 = n / 4;

    zero_kernel<<<(TBINS + 255) / 256, 256>>>();

    int blocks = (n4 + 255) / 256;
    if (blocks < 1) blocks = 1;
    accum_kernel<<<blocks, 256>>>((const float4*)inp, (const int4*)tgt,
                                  (const int4*)ev, n4, n);

    blocksum_kernel<<<NSCAN_BLOCKS, SCAN_TPB>>>();
    offset_kernel<<<1, 32>>>();
    efron_kernel<<<NSCAN_BLOCKS, SCAN_TPB>>>();
    finalize_kernel<<<1, 1>>>(out);
}

// round 4
// speedup vs baseline: 1.2447x; 1.2447x over previous
#include <cuda_runtime.h>
#include <cuda_bf16.h>

#define TBINS 100000
#define SCAN_TPB 512
#define NSCAN_BLOCKS ((TBINS + SCAN_TPB - 1) / SCAN_TPB)   // 196

// bins[t] = { sum(exp(lh)), sum(exp(lh)*ev), sum(lh*ev), sum(ev) }
// Invariant: g_bins is all-zero at kernel_launch entry (zero at static init,
// re-zeroed by efron_kernel after consumption on every call).
__device__ float4 g_bins[TBINS];
__device__ double g_blockSum[NSCAN_BLOCKS];
__device__ double g_pll_sum;   // zero at entry; reset by finalize_kernel
__device__ int    g_cnt;       // zero at entry; reset by finalize_kernel

// ---------------------------------------------------------------- accumulate
__device__ __forceinline__ void acc_one(float lh, int t, int e) {
    float hz = expf(lh);
    float4* p = &g_bins[t];
    if (e) {
        // A+=hz, ties+=hz, lognom+=lh, m+=1
        asm volatile(
            "red.global.add.v4.f32 [%0], {%1, %2, %3, %4};"
            :: "l"(p), "f"(hz), "f"(hz), "f"(lh), "f"(1.0f)
            : "memory");
    } else {
        // only the risk-set sum changes
        asm volatile(
            "red.global.add.f32 [%0], %1;"
            :: "l"(p), "f"(hz)
            : "memory");
    }
}

__global__ void accum_kernel(const float4* __restrict__ in,
                             const int4*  __restrict__ tgt,
                             const int4*  __restrict__ ev,
                             int n4, int n) {
    int i = blockIdx.x * blockDim.x + threadIdx.x;
    if (i < n4) {
        float4 lh = in[i];
        int4   t  = tgt[i];
        int4   e  = ev[i];
        acc_one(lh.x, t.x, e.x);
        acc_one(lh.y, t.y, e.y);
        acc_one(lh.z, t.z, e.z);
        acc_one(lh.w, t.w, e.w);
    }
    // tail (n not multiple of 4) handled by global thread 0
    if (i == 0) {
        const float* fin = (const float*)in;
        const int*   it  = (const int*)tgt;
        const int*   ie  = (const int*)ev;
        for (int k = n4 * 4; k < n; ++k) acc_one(fin[k], it[k], ie[k]);
    }
}

// ---------------------------------------------------------------- block sums of A
__global__ void blocksum_kernel() {
    __shared__ double s[SCAN_TPB];
    int b = blockIdx.x, i = threadIdx.x;
    int t = b * SCAN_TPB + i;
    s[i] = (t < TBINS) ? (double)g_bins[t].x : 0.0;
    __syncthreads();
    for (int off = SCAN_TPB / 2; off > 0; off >>= 1) {
        if (i < off) s[i] += s[i + off];
        __syncthreads();
    }
    if (i == 0) g_blockSum[b] = s[0];
}

// ------------------------------------------- suffix + Efron terms (offset fused)
__global__ void efron_kernel() {
    __shared__ double s[SCAN_TPB];
    __shared__ double s_off;
    int b = blockIdx.x, i = threadIdx.x;
    int t = b * SCAN_TPB + i;

    float4 bin = (t < TBINS) ? g_bins[t] : make_float4(0.f, 0.f, 0.f, 0.f);
    // restore the all-zero invariant for the next call
    if (t < TBINS) g_bins[t] = make_float4(0.f, 0.f, 0.f, 0.f);

    // ---- cross-block suffix offset: sum of g_blockSum[j] for j > b
    double off = 0.0;
    for (int j = b + 1 + i; j < NSCAN_BLOCKS; j += SCAN_TPB)
        off += g_blockSum[j];
    s[i] = off;
    __syncthreads();
    for (int o = SCAN_TPB / 2; o > 0; o >>= 1) {
        if (i < o) s[i] += s[i + o];
        __syncthreads();
    }
    if (i == 0) s_off = s[0];
    __syncthreads();
    double blockOff = s_off;

    // ---- in-block suffix-inclusive scan of A (Hillis-Steele)
    s[i] = (double)bin.x;
    __syncthreads();
    for (int o = 1; o < SCAN_TPB; o <<= 1) {
        double v = s[i];
        if (i + o < SCAN_TPB) v += s[i + o];
        __syncthreads();
        s[i] = v;
        __syncthreads();
    }
    double D = s[i] + blockOff;   // risk-set sum for time t

    // ---- Efron correction terms
    double pll = 0.0;
    int inc = 0;
    int m = (int)(bin.w + 0.5f);
    if (t < TBINS && m > 0) {
        float Df   = (float)D;
        float T    = bin.y;
        float invm = 1.0f / (float)m;
        float ld   = 0.0f;
        for (int l = 0; l < m; ++l)
            ld += logf(Df - ((float)l * invm) * T);
        pll = (double)bin.z - (double)ld;
        inc = 1;
    }

    int cnt = __syncthreads_count(inc);

    s[i] = pll;
    __syncthreads();
    for (int o = SCAN_TPB / 2; o > 0; o >>= 1) {
        if (i < o) s[i] += s[i + o];
        __syncthreads();
    }
    if (i == 0) {
        atomicAdd(&g_pll_sum, s[0]);
        atomicAdd(&g_cnt, cnt);
    }
}

// ---------------------------------------------------------------- finalize
__global__ void finalize_kernel(float* out) {
    out[0] = (float)(-(g_pll_sum / (double)g_cnt));
    // restore invariant for next call
    g_pll_sum = 0.0;
    g_cnt = 0;
}

// ---------------------------------------------------------------- launcher
extern "C" void kernel_launch(void* const* d_in, const int* in_sizes, int n_in,
                              void* d_out, int out_size) {
    const float* inp = (const float*)d_in[0];
    const int*   tgt = (const int*)d_in[1];
    const int*   ev  = (const int*)d_in[2];
    float* out = (float*)d_out;
    int n  = in_sizes[0];
    int n4 = n / 4;

    int blocks = (n4 + 255) / 256;
    if (blocks < 1) blocks = 1;
    accum_kernel<<<blocks, 256>>>((const float4*)inp, (const int4*)tgt,
                                  (const int4*)ev, n4, n);

    blocksum_kernel<<<NSCAN_BLOCKS, SCAN_TPB>>>();
    efron_kernel<<<NSCAN_BLOCKS, SCAN_TPB>>>();
    finalize_kernel<<<1, 1>>>(out);
}